// round 15
// baseline (speedup 1.0000x reference)
#include <cuda_runtime.h>

#define M_ENT 8000
#define NTOK  32
#define BSZ   64
#define DIM   256

#define OK_OFF 0
#define LE_OFF (BSZ*DIM)                 // 16384
#define CB_OFF (LE_OFF + BSZ*M_ENT)      // 528384

// scratch (device globals — no allocations allowed)
__device__ float g_vq[BSZ*DIM];     // vq, plain row-major [b][k]
__device__ float g_pe[M_ENT*BSZ];   // prob_e transposed: [m][b]

// ---------------------------------------------------------------------------
// tf32 helpers
// ---------------------------------------------------------------------------
__device__ __forceinline__ unsigned f2tf(float v){
    unsigned r; asm("cvt.rna.tf32.f32 %0, %1;" : "=r"(r) : "f"(v)); return r;
}
__device__ __forceinline__ void mma8(float& c0, float& c1, float& c2, float& c3,
                                     unsigned a0, unsigned a1, unsigned a2, unsigned a3,
                                     unsigned b0, unsigned b1){
    asm volatile("mma.sync.aligned.m16n8k8.row.col.f32.tf32.tf32.f32 "
                 "{%0,%1,%2,%3},{%4,%5,%6,%7},{%8,%9},{%0,%1,%2,%3};"
                 : "+f"(c0), "+f"(c1), "+f"(c2), "+f"(c3)
                 : "r"(a0), "r"(a1), "r"(a2), "r"(a3), "r"(b0), "r"(b1));
}

// ---------------------------------------------------------------------------
// K0: zero the accumulated output regions (o_k, combined)
// ---------------------------------------------------------------------------
__global__ void k_zero(float* out){
    int i = blockIdx.x * blockDim.x + threadIdx.x;
    if (i < BSZ*DIM){ out[OK_OFF + i] = 0.f; out[CB_OFF + i] = 0.f; }
}

// ---------------------------------------------------------------------------
// K1: vq = query @ qproj_w.T + qproj_b  (plain [b][k] layout)
// ---------------------------------------------------------------------------
__global__ void k_vq(const float* __restrict__ query,
                     const float* __restrict__ qw,
                     const float* __restrict__ qb){
    __shared__ float q_s[DIM];
    int b = blockIdx.x, j = threadIdx.x;
    q_s[j] = query[b*DIM + j];
    __syncthreads();
    const float4* w4 = reinterpret_cast<const float4*>(qw) + j*(DIM/4);
    const float4* q4 = reinterpret_cast<const float4*>(q_s);
    float acc = qb[j];
    #pragma unroll 8
    for (int f = 0; f < DIM/4; f++){
        float4 w = w4[f]; float4 q = q4[f];
        acc += w.x*q.x + w.y*q.y + w.z*q.z + w.w*q.w;
    }
    g_vq[b*DIM + j] = acc;
}

// ---------------------------------------------------------------------------
// K2: logits_e[b,m] = query[b] . keys_e[m]  (fp32, exact output — unchanged)
// ---------------------------------------------------------------------------
__global__ __launch_bounds__(256)
void k_logits(const int* __restrict__ keys,
              const float* __restrict__ query,
              const float* __restrict__ wordemb,
              float* __restrict__ out){
    extern __shared__ float sm[];
    float* q_s  = sm;               // 16384 floats
    float* ke_s = sm + BSZ*DIM;     // 8192 floats (swizzled)
    int tid = threadIdx.x;
    int m0 = blockIdx.x * NTOK;

    float4* q4s = (float4*)q_s;
    const float4* q4g = (const float4*)query;
    for (int i = tid; i < BSZ*DIM/4; i += 256) q4s[i] = q4g[i];

    {   // gather keys_e (row = lane, quads = warp)
        int n = tid & 31, seg = tid >> 5;
        int id = keys[m0 + n];
        const float4* src = (const float4*)wordemb + (size_t)id*(DIM/4);
        float4* t4 = (float4*)ke_s;
        float4 z = make_float4(0.f,0.f,0.f,0.f);
        #pragma unroll
        for (int q = 0; q < 8; q++){
            int f = seg*8 + q;
            float4 v = (id != 0) ? src[f] : z;
            t4[n*64 + (f ^ (n & 7))] = v;
        }
    }
    __syncthreads();

    int w = tid >> 5, mm = tid & 31;
    const float4* t4 = (const float4*)ke_s;
    const float4* q4 = (const float4*)q_s;
    float lg[8];
    #pragma unroll
    for (int i = 0; i < 8; i++) lg[i] = 0.f;
    #pragma unroll 4
    for (int f = 0; f < 64; f++){
        float4 t = t4[mm*64 + (f ^ (mm & 7))];
        #pragma unroll
        for (int i = 0; i < 8; i++){
            float4 q = q4[(w*8 + i)*64 + f];
            lg[i] += t.x*q.x + t.y*q.y + t.z*q.z + t.w*q.w;
        }
    }
    float* le = out + LE_OFF;
    #pragma unroll
    for (int i = 0; i < 8; i++)
        le[(size_t)(w*8 + i)*M_ENT + m0 + mm] = lg[i];
}

// ---------------------------------------------------------------------------
// K3: row softmax over m; single global read pass (values cached in regs)
// ---------------------------------------------------------------------------
__global__ void k_softmax(const float* __restrict__ out){
    __shared__ float red[256];
    int b = blockIdx.x, tid = threadIdx.x;
    const float* row = out + LE_OFF + (size_t)b*M_ENT;
    float x[32];
    float mx = -3.4e38f;
    #pragma unroll
    for (int i = 0; i < 32; i++){
        int m = tid + 256*i;
        x[i] = (m < M_ENT) ? row[m] : -3.4e38f;
        mx = fmaxf(mx, x[i]);
    }
    red[tid] = mx; __syncthreads();
    for (int s = 128; s; s >>= 1){ if (tid < s) red[tid] = fmaxf(red[tid], red[tid+s]); __syncthreads(); }
    float gmx = red[0];
    __syncthreads();
    float sum = 0.f;
    #pragma unroll
    for (int i = 0; i < 32; i++){
        x[i] = __expf(x[i] - gmx);      // exp(-huge) -> 0, safe for padding
        sum += x[i];
    }
    red[tid] = sum; __syncthreads();
    for (int s = 128; s; s >>= 1){ if (tid < s) red[tid] += red[tid+s]; __syncthreads(); }
    float inv = 1.f / red[0];
    #pragma unroll
    for (int i = 0; i < 32; i++){
        int m = tid + 256*i;
        if (m < M_ENT) g_pe[(size_t)m*BSZ + b] = x[i] * inv;
    }
}

// ---------------------------------------------------------------------------
// K4: main — per entry m: gather 32x256 tile, logits via split-tf32 MMA,
// per-b token softmax (smem, in-place), weighted sum via tf32 MMA with
// register-resident C accumulated over all entries. One atomic sweep at end.
// warp w: b-tile = (w>>1)*16 (stage1 & stage3); stage1 n-half / stage3 d-half = w&1.
// ---------------------------------------------------------------------------
#define VSTR 260
#define TSTR 260
#define LSTR 36
#define V_SOF 0
#define T_SOF (BSZ*VSTR)               // 16640
#define L_SOF (T_SOF + NTOK*TSTR)      // 24960
#define PE_SOF (L_SOF + BSZ*LSTR)      // 27264
#define MAIN_SMEM_FLOATS (PE_SOF + BSZ)   // 27328 -> 109312 B

__global__ __launch_bounds__(256, 2)
void k_main(const int* __restrict__ entries,
            const float* __restrict__ wordemb,
            float* __restrict__ out){
    extern __shared__ float sm[];
    float* Vs = sm + V_SOF;
    float* Ts = sm + T_SOF;
    float* Ls = sm + L_SOF;
    float* pe = sm + PE_SOF;
    int tid = threadIdx.x, w = tid >> 5, lane = tid & 31;
    int gid = lane >> 2, tin = lane & 3;

    // stage V (fp32) into padded smem once
    for (int i4 = tid; i4 < BSZ*DIM/4; i4 += 256){
        int b = i4 >> 6, kq = i4 & 63;
        ((float4*)(Vs + b*VSTR))[kq] = ((const float4*)g_vq)[i4];
    }

    const int br    = (w >> 1) * 16;   // b-tile base
    const int nh    = (w & 1);         // stage1 n-half
    const int dbase = (w & 1) * 128;   // stage3 d-half

    float4 acc[16];                    // C2: 16b x 128d per warp
    #pragma unroll
    for (int i = 0; i < 16; i++) acc[i] = make_float4(0.f,0.f,0.f,0.f);

    for (int m = blockIdx.x; m < M_ENT; m += gridDim.x){
        __syncthreads();   // protect Ts/Ls from previous iteration readers
        {   // gather entry token tile (row = lane), mask pad idx
            int id = entries[m*NTOK + lane];
            const float4* src = (const float4*)wordemb + (size_t)id*(DIM/4);
            float4 z = make_float4(0.f,0.f,0.f,0.f);
            float4* dst = (float4*)(Ts + lane*TSTR);
            #pragma unroll
            for (int q = 0; q < 8; q++){
                int f = w*8 + q;
                dst[f] = (id != 0) ? src[f] : z;
            }
        }
        if (tid < BSZ) pe[tid] = g_pe[(size_t)m*BSZ + tid];
        __syncthreads();

        // ---- stage 1: L[16b x 16n] = V . T^T, split-tf32 (Vh*Th + Vl*Th + Vh*Tl)
        float4 L0 = make_float4(0.f,0.f,0.f,0.f);
        float4 L1 = make_float4(0.f,0.f,0.f,0.f);
        const float* vr0 = Vs + (br+gid)*VSTR + tin;
        const float* vr1 = Vs + (br+gid+8)*VSTR + tin;
        const float* tr0 = Ts + (nh*16+gid)*TSTR + tin;
        const float* tr1 = Ts + (nh*16+8+gid)*TSTR + tin;
        #pragma unroll 4
        for (int ks = 0; ks < 32; ks++){
            int k0 = ks*8;
            float v0 = vr0[k0], v1 = vr1[k0], v2 = vr0[k0+4], v3 = vr1[k0+4];
            unsigned ah0 = f2tf(v0), ah1 = f2tf(v1), ah2 = f2tf(v2), ah3 = f2tf(v3);
            unsigned al0 = __float_as_uint(v0 - __uint_as_float(ah0));
            unsigned al1 = __float_as_uint(v1 - __uint_as_float(ah1));
            unsigned al2 = __float_as_uint(v2 - __uint_as_float(ah2));
            unsigned al3 = __float_as_uint(v3 - __uint_as_float(ah3));
            // n-tile 0
            {
                float t0 = tr0[k0], t1 = tr0[k0+4];
                unsigned bh0 = f2tf(t0), bh1 = f2tf(t1);
                unsigned bl0 = __float_as_uint(t0 - __uint_as_float(bh0));
                unsigned bl1 = __float_as_uint(t1 - __uint_as_float(bh1));
                mma8(L0.x,L0.y,L0.z,L0.w, ah0,ah1,ah2,ah3, bh0,bh1);
                mma8(L0.x,L0.y,L0.z,L0.w, al0,al1,al2,al3, bh0,bh1);
                mma8(L0.x,L0.y,L0.z,L0.w, ah0,ah1,ah2,ah3, bl0,bl1);
            }
            // n-tile 1
            {
                float t0 = tr1[k0], t1 = tr1[k0+4];
                unsigned bh0 = f2tf(t0), bh1 = f2tf(t1);
                unsigned bl0 = __float_as_uint(t0 - __uint_as_float(bh0));
                unsigned bl1 = __float_as_uint(t1 - __uint_as_float(bh1));
                mma8(L1.x,L1.y,L1.z,L1.w, ah0,ah1,ah2,ah3, bh0,bh1);
                mma8(L1.x,L1.y,L1.z,L1.w, al0,al1,al2,al3, bh0,bh1);
                mma8(L1.x,L1.y,L1.z,L1.w, ah0,ah1,ah2,ah3, bl0,bl1);
            }
        }
        {   // write logits to smem (C-frag layout)
            float* lw0 = Ls + (br+gid)*LSTR;
            float* lw1 = Ls + (br+gid+8)*LSTR;
            int nc = nh*16 + 2*tin;
            lw0[nc]   = L0.x; lw0[nc+1] = L0.y;
            lw1[nc]   = L0.z; lw1[nc+1] = L0.w;
            lw0[nc+8] = L1.x; lw0[nc+9] = L1.y;
            lw1[nc+8] = L1.z; lw1[nc+9] = L1.w;
        }
        __syncthreads();

        // ---- softmax over 32 tokens per b row; fold in prob_e; in place.
        // quad of lanes per row: warp w handles rows w*8 .. w*8+7
        {
            int srow = w*8 + (lane >> 2);
            float* lr = Ls + srow*LSTR + (lane & 3)*8;
            float4 xa = *(float4*)lr;
            float4 xb = *(float4*)(lr + 4);
            float mx = fmaxf(fmaxf(fmaxf(xa.x,xa.y), fmaxf(xa.z,xa.w)),
                             fmaxf(fmaxf(xb.x,xb.y), fmaxf(xb.z,xb.w)));
            mx = fmaxf(mx, __shfl_xor_sync(0xffffffffu, mx, 1));
            mx = fmaxf(mx, __shfl_xor_sync(0xffffffffu, mx, 2));
            xa.x = __expf(xa.x - mx); xa.y = __expf(xa.y - mx);
            xa.z = __expf(xa.z - mx); xa.w = __expf(xa.w - mx);
            xb.x = __expf(xb.x - mx); xb.y = __expf(xb.y - mx);
            xb.z = __expf(xb.z - mx); xb.w = __expf(xb.w - mx);
            float s = (xa.x+xa.y+xa.z+xa.w) + (xb.x+xb.y+xb.z+xb.w);
            s += __shfl_xor_sync(0xffffffffu, s, 1);
            s += __shfl_xor_sync(0xffffffffu, s, 2);
            float sc = __fdividef(pe[srow], s);
            xa.x *= sc; xa.y *= sc; xa.z *= sc; xa.w *= sc;
            xb.x *= sc; xb.y *= sc; xb.z *= sc; xb.w *= sc;
            *(float4*)lr     = xa;
            *(float4*)(lr+4) = xb;
        }
        __syncthreads();

        // ---- stage 3: C2[16b x 128d] += P[16b x 32n] . T[32n x 128d]  (tf32)
        #pragma unroll
        for (int kn = 0; kn < 4; kn++){
            int kn0 = kn*8;
            float p0 = Ls[(br+gid  )*LSTR + kn0 + tin];
            float p1 = Ls[(br+gid+8)*LSTR + kn0 + tin];
            float p2 = Ls[(br+gid  )*LSTR + kn0 + tin + 4];
            float p3 = Ls[(br+gid+8)*LSTR + kn0 + tin + 4];
            unsigned pa0 = f2tf(p0), pa1 = f2tf(p1), pa2 = f2tf(p2), pa3 = f2tf(p3);
            const float* tb0 = Ts + (kn0+tin  )*TSTR + dbase + gid;
            const float* tb1 = Ts + (kn0+tin+4)*TSTR + dbase + gid;
            #pragma unroll
            for (int dt = 0; dt < 16; dt++){
                unsigned ub0 = f2tf(tb0[dt*8]);
                unsigned ub1 = f2tf(tb1[dt*8]);
                mma8(acc[dt].x, acc[dt].y, acc[dt].z, acc[dt].w,
                     pa0, pa1, pa2, pa3, ub0, ub1);
            }
        }
    }

    // epilogue: one atomic sweep per block
    float* comb = out + CB_OFF;
    #pragma unroll
    for (int dt = 0; dt < 16; dt++){
        int d0 = dbase + dt*8 + 2*tin;
        atomicAdd(&comb[(br+gid  )*DIM + d0    ], acc[dt].x);
        atomicAdd(&comb[(br+gid  )*DIM + d0 + 1], acc[dt].y);
        atomicAdd(&comb[(br+gid+8)*DIM + d0    ], acc[dt].z);
        atomicAdd(&comb[(br+gid+8)*DIM + d0 + 1], acc[dt].w);
    }
}

// ---------------------------------------------------------------------------
// K5: o_k = prob_e @ keys_e. block owns 50 m; thread = d; acc over 64 b.
// ---------------------------------------------------------------------------
__global__ __launch_bounds__(256)
void k_ok(const int* __restrict__ keys,
          const float* __restrict__ wordemb,
          float* __restrict__ out){
    __shared__ float pe_s[50*BSZ];
    int tid = threadIdx.x;
    int m0 = blockIdx.x * 50;
    for (int i = tid; i < 50*BSZ; i += 256) pe_s[i] = g_pe[(size_t)m0*BSZ + i];
    __syncthreads();
    int d = tid;
    float acc[BSZ];
    #pragma unroll
    for (int b = 0; b < BSZ; b++) acc[b] = 0.f;
    for (int mm = 0; mm < 50; mm++){
        int id = keys[m0 + mm];
        float ke = (id != 0) ? wordemb[(size_t)id*DIM + d] : 0.f;
        const float4* pr = (const float4*)(pe_s + mm*BSZ);
        #pragma unroll
        for (int b4 = 0; b4 < 16; b4++){
            float4 pv = pr[b4];
            acc[4*b4+0] += pv.x*ke; acc[4*b4+1] += pv.y*ke;
            acc[4*b4+2] += pv.z*ke; acc[4*b4+3] += pv.w*ke;
        }
    }
    float* ok = out + OK_OFF;
    #pragma unroll
    for (int b = 0; b < BSZ; b++) atomicAdd(&ok[b*DIM + d], acc[b]);
}

// ---------------------------------------------------------------------------
extern "C" void kernel_launch(void* const* d_in, const int* in_sizes, int n_in,
                              void* d_out, int out_size){
    const int*   keys    = (const int*)  d_in[0];
    const int*   entries = (const int*)  d_in[1];
    const float* query   = (const float*)d_in[2];
    const float* wordemb = (const float*)d_in[3];
    const float* qw      = (const float*)d_in[4];
    const float* qb      = (const float*)d_in[5];
    float* out = (float*)d_out;

    const int smem_logits = (BSZ*DIM + NTOK*DIM) * 4;      // 98304
    const int smem_main   = MAIN_SMEM_FLOATS * 4;          // 109312
    cudaFuncSetAttribute(k_logits, cudaFuncAttributeMaxDynamicSharedMemorySize, smem_logits);
    cudaFuncSetAttribute(k_main,   cudaFuncAttributeMaxDynamicSharedMemorySize, smem_main);

    k_zero   <<<(BSZ*DIM + 255)/256, 256>>>(out);
    k_vq     <<<BSZ, DIM>>>(query, qw, qb);
    k_logits <<<M_ENT/NTOK, 256, smem_logits>>>(keys, query, wordemb, out);
    k_softmax<<<BSZ, 256>>>(out);
    k_main   <<<296, 256, smem_main>>>(entries, wordemb, out);
    k_ok     <<<M_ENT/50, 256>>>(keys, wordemb, out);
}

// round 16
// speedup vs baseline: 1.0069x; 1.0069x over previous
#include <cuda_runtime.h>

#define M_ENT 8000
#define NTOK  32
#define BSZ   64
#define DIM   256

#define OK_OFF 0
#define LE_OFF (BSZ*DIM)                 // 16384
#define CB_OFF (LE_OFF + BSZ*M_ENT)      // 528384

// scratch (device globals — no allocations allowed)
__device__ float g_vq[BSZ*DIM];     // vq, plain row-major [b][k]
__device__ float g_pe[M_ENT*BSZ];   // prob_e transposed: [m][b]

// ---------------------------------------------------------------------------
// tf32 helpers
// ---------------------------------------------------------------------------
__device__ __forceinline__ unsigned f2tf(float v){
    unsigned r; asm("cvt.rna.tf32.f32 %0, %1;" : "=r"(r) : "f"(v)); return r;
}
__device__ __forceinline__ void mma8(float& c0, float& c1, float& c2, float& c3,
                                     unsigned a0, unsigned a1, unsigned a2, unsigned a3,
                                     unsigned b0, unsigned b1){
    asm volatile("mma.sync.aligned.m16n8k8.row.col.f32.tf32.tf32.f32 "
                 "{%0,%1,%2,%3},{%4,%5,%6,%7},{%8,%9},{%0,%1,%2,%3};"
                 : "+f"(c0), "+f"(c1), "+f"(c2), "+f"(c3)
                 : "r"(a0), "r"(a1), "r"(a2), "r"(a3), "r"(b0), "r"(b1));
}

// ---------------------------------------------------------------------------
// K0: zero the accumulated output regions (o_k, combined)
// ---------------------------------------------------------------------------
__global__ void k_zero(float* out){
    int i = blockIdx.x * blockDim.x + threadIdx.x;
    if (i < BSZ*DIM){ out[OK_OFF + i] = 0.f; out[CB_OFF + i] = 0.f; }
}

// ---------------------------------------------------------------------------
// K1: vq = query @ qproj_w.T + qproj_b  (plain [b][k] layout)
// ---------------------------------------------------------------------------
__global__ void k_vq(const float* __restrict__ query,
                     const float* __restrict__ qw,
                     const float* __restrict__ qb){
    __shared__ float q_s[DIM];
    int b = blockIdx.x, j = threadIdx.x;
    q_s[j] = query[b*DIM + j];
    __syncthreads();
    const float4* w4 = reinterpret_cast<const float4*>(qw) + j*(DIM/4);
    const float4* q4 = reinterpret_cast<const float4*>(q_s);
    float acc = qb[j];
    #pragma unroll 8
    for (int f = 0; f < DIM/4; f++){
        float4 w = w4[f]; float4 q = q4[f];
        acc += w.x*q.x + w.y*q.y + w.z*q.z + w.w*q.w;
    }
    g_vq[b*DIM + j] = acc;
}

// ---------------------------------------------------------------------------
// K2: logits_e[b,m] = query[b] . keys_e[m]  (fp32, exact output — unchanged)
// ---------------------------------------------------------------------------
__global__ __launch_bounds__(256)
void k_logits(const int* __restrict__ keys,
              const float* __restrict__ query,
              const float* __restrict__ wordemb,
              float* __restrict__ out){
    extern __shared__ float sm[];
    float* q_s  = sm;               // 16384 floats
    float* ke_s = sm + BSZ*DIM;     // 8192 floats (swizzled)
    int tid = threadIdx.x;
    int m0 = blockIdx.x * NTOK;

    float4* q4s = (float4*)q_s;
    const float4* q4g = (const float4*)query;
    for (int i = tid; i < BSZ*DIM/4; i += 256) q4s[i] = q4g[i];

    {   // gather keys_e (row = lane, quads = warp)
        int n = tid & 31, seg = tid >> 5;
        int id = keys[m0 + n];
        const float4* src = (const float4*)wordemb + (size_t)id*(DIM/4);
        float4* t4 = (float4*)ke_s;
        float4 z = make_float4(0.f,0.f,0.f,0.f);
        #pragma unroll
        for (int q = 0; q < 8; q++){
            int f = seg*8 + q;
            float4 v = (id != 0) ? src[f] : z;
            t4[n*64 + (f ^ (n & 7))] = v;
        }
    }
    __syncthreads();

    int w = tid >> 5, mm = tid & 31;
    const float4* t4 = (const float4*)ke_s;
    const float4* q4 = (const float4*)q_s;
    float lg[8];
    #pragma unroll
    for (int i = 0; i < 8; i++) lg[i] = 0.f;
    #pragma unroll 4
    for (int f = 0; f < 64; f++){
        float4 t = t4[mm*64 + (f ^ (mm & 7))];
        #pragma unroll
        for (int i = 0; i < 8; i++){
            float4 q = q4[(w*8 + i)*64 + f];
            lg[i] += t.x*q.x + t.y*q.y + t.z*q.z + t.w*q.w;
        }
    }
    float* le = out + LE_OFF;
    #pragma unroll
    for (int i = 0; i < 8; i++)
        le[(size_t)(w*8 + i)*M_ENT + m0 + mm] = lg[i];
}

// ---------------------------------------------------------------------------
// K3: row softmax over m; single global read pass (values cached in regs)
// ---------------------------------------------------------------------------
__global__ void k_softmax(const float* __restrict__ out){
    __shared__ float red[256];
    int b = blockIdx.x, tid = threadIdx.x;
    const float* row = out + LE_OFF + (size_t)b*M_ENT;
    float x[32];
    float mx = -3.4e38f;
    #pragma unroll
    for (int i = 0; i < 32; i++){
        int m = tid + 256*i;
        x[i] = (m < M_ENT) ? row[m] : -3.4e38f;
        mx = fmaxf(mx, x[i]);
    }
    red[tid] = mx; __syncthreads();
    for (int s = 128; s; s >>= 1){ if (tid < s) red[tid] = fmaxf(red[tid], red[tid+s]); __syncthreads(); }
    float gmx = red[0];
    __syncthreads();
    float sum = 0.f;
    #pragma unroll
    for (int i = 0; i < 32; i++){
        x[i] = __expf(x[i] - gmx);      // exp(-huge) -> 0, safe for padding
        sum += x[i];
    }
    red[tid] = sum; __syncthreads();
    for (int s = 128; s; s >>= 1){ if (tid < s) red[tid] += red[tid+s]; __syncthreads(); }
    float inv = 1.f / red[0];
    #pragma unroll
    for (int i = 0; i < 32; i++){
        int m = tid + 256*i;
        if (m < M_ENT) g_pe[(size_t)m*BSZ + b] = x[i] * inv;
    }
}

// ---------------------------------------------------------------------------
// K4: main — per entry m: gather 32x256 tile, logits via split-tf32 MMA,
// per-b token softmax (smem, in-place), weighted sum via tf32 MMA with
// register-resident C accumulated over all entries. One atomic sweep at end.
// warp w: b-tile = (w>>1)*16 (stage1 & stage3); stage1 n-half / stage3 d-half = w&1.
// ---------------------------------------------------------------------------
#define VSTR 260
#define TSTR 260
#define LSTR 36
#define V_SOF 0
#define T_SOF (BSZ*VSTR)               // 16640
#define L_SOF (T_SOF + NTOK*TSTR)      // 24960
#define PE_SOF (L_SOF + BSZ*LSTR)      // 27264
#define MAIN_SMEM_FLOATS (PE_SOF + BSZ)   // 27328 -> 109312 B

__global__ __launch_bounds__(256, 2)
void k_main(const int* __restrict__ entries,
            const float* __restrict__ wordemb,
            float* __restrict__ out){
    extern __shared__ float sm[];
    float* Vs = sm + V_SOF;
    float* Ts = sm + T_SOF;
    float* Ls = sm + L_SOF;
    float* pe = sm + PE_SOF;
    int tid = threadIdx.x, w = tid >> 5, lane = tid & 31;
    int gid = lane >> 2, tin = lane & 3;

    // stage V (fp32) into padded smem once
    for (int i4 = tid; i4 < BSZ*DIM/4; i4 += 256){
        int b = i4 >> 6, kq = i4 & 63;
        ((float4*)(Vs + b*VSTR))[kq] = ((const float4*)g_vq)[i4];
    }

    const int br    = (w >> 1) * 16;   // b-tile base
    const int nh    = (w & 1);         // stage1 n-half
    const int dbase = (w & 1) * 128;   // stage3 d-half

    float4 acc[16];                    // C2: 16b x 128d per warp
    #pragma unroll
    for (int i = 0; i < 16; i++) acc[i] = make_float4(0.f,0.f,0.f,0.f);

    for (int m = blockIdx.x; m < M_ENT; m += gridDim.x){
        __syncthreads();   // protect Ts/Ls from previous iteration readers
        {   // gather entry token tile (row = lane), mask pad idx
            int id = entries[m*NTOK + lane];
            const float4* src = (const float4*)wordemb + (size_t)id*(DIM/4);
            float4 z = make_float4(0.f,0.f,0.f,0.f);
            float4* dst = (float4*)(Ts + lane*TSTR);
            #pragma unroll
            for (int q = 0; q < 8; q++){
                int f = w*8 + q;
                dst[f] = (id != 0) ? src[f] : z;
            }
        }
        if (tid < BSZ) pe[tid] = g_pe[(size_t)m*BSZ + tid];
        __syncthreads();

        // ---- stage 1: L[16b x 16n] = V . T^T, split-tf32 (Vh*Th + Vl*Th + Vh*Tl)
        float4 L0 = make_float4(0.f,0.f,0.f,0.f);
        float4 L1 = make_float4(0.f,0.f,0.f,0.f);
        const float* vr0 = Vs + (br+gid)*VSTR + tin;
        const float* vr1 = Vs + (br+gid+8)*VSTR + tin;
        const float* tr0 = Ts + (nh*16+gid)*TSTR + tin;
        const float* tr1 = Ts + (nh*16+8+gid)*TSTR + tin;
        #pragma unroll 4
        for (int ks = 0; ks < 32; ks++){
            int k0 = ks*8;
            float v0 = vr0[k0], v1 = vr1[k0], v2 = vr0[k0+4], v3 = vr1[k0+4];
            unsigned ah0 = f2tf(v0), ah1 = f2tf(v1), ah2 = f2tf(v2), ah3 = f2tf(v3);
            unsigned al0 = __float_as_uint(v0 - __uint_as_float(ah0));
            unsigned al1 = __float_as_uint(v1 - __uint_as_float(ah1));
            unsigned al2 = __float_as_uint(v2 - __uint_as_float(ah2));
            unsigned al3 = __float_as_uint(v3 - __uint_as_float(ah3));
            // n-tile 0
            {
                float t0 = tr0[k0], t1 = tr0[k0+4];
                unsigned bh0 = f2tf(t0), bh1 = f2tf(t1);
                unsigned bl0 = __float_as_uint(t0 - __uint_as_float(bh0));
                unsigned bl1 = __float_as_uint(t1 - __uint_as_float(bh1));
                mma8(L0.x,L0.y,L0.z,L0.w, ah0,ah1,ah2,ah3, bh0,bh1);
                mma8(L0.x,L0.y,L0.z,L0.w, al0,al1,al2,al3, bh0,bh1);
                mma8(L0.x,L0.y,L0.z,L0.w, ah0,ah1,ah2,ah3, bl0,bl1);
            }
            // n-tile 1
            {
                float t0 = tr1[k0], t1 = tr1[k0+4];
                unsigned bh0 = f2tf(t0), bh1 = f2tf(t1);
                unsigned bl0 = __float_as_uint(t0 - __uint_as_float(bh0));
                unsigned bl1 = __float_as_uint(t1 - __uint_as_float(bh1));
                mma8(L1.x,L1.y,L1.z,L1.w, ah0,ah1,ah2,ah3, bh0,bh1);
                mma8(L1.x,L1.y,L1.z,L1.w, al0,al1,al2,al3, bh0,bh1);
                mma8(L1.x,L1.y,L1.z,L1.w, ah0,ah1,ah2,ah3, bl0,bl1);
            }
        }
        {   // write logits to smem (C-frag layout)
            float* lw0 = Ls + (br+gid)*LSTR;
            float* lw1 = Ls + (br+gid+8)*LSTR;
            int nc = nh*16 + 2*tin;
            lw0[nc]   = L0.x; lw0[nc+1] = L0.y;
            lw1[nc]   = L0.z; lw1[nc+1] = L0.w;
            lw0[nc+8] = L1.x; lw0[nc+9] = L1.y;
            lw1[nc+8] = L1.z; lw1[nc+9] = L1.w;
        }
        __syncthreads();

        // ---- softmax over 32 tokens per b row; fold in prob_e; in place.
        // quad of lanes per row: warp w handles rows w*8 .. w*8+7
        {
            int srow = w*8 + (lane >> 2);
            float* lr = Ls + srow*LSTR + (lane & 3)*8;
            float4 xa = *(float4*)lr;
            float4 xb = *(float4*)(lr + 4);
            float mx = fmaxf(fmaxf(fmaxf(xa.x,xa.y), fmaxf(xa.z,xa.w)),
                             fmaxf(fmaxf(xb.x,xb.y), fmaxf(xb.z,xb.w)));
            mx = fmaxf(mx, __shfl_xor_sync(0xffffffffu, mx, 1));
            mx = fmaxf(mx, __shfl_xor_sync(0xffffffffu, mx, 2));
            xa.x = __expf(xa.x - mx); xa.y = __expf(xa.y - mx);
            xa.z = __expf(xa.z - mx); xa.w = __expf(xa.w - mx);
            xb.x = __expf(xb.x - mx); xb.y = __expf(xb.y - mx);
            xb.z = __expf(xb.z - mx); xb.w = __expf(xb.w - mx);
            float s = (xa.x+xa.y+xa.z+xa.w) + (xb.x+xb.y+xb.z+xb.w);
            s += __shfl_xor_sync(0xffffffffu, s, 1);
            s += __shfl_xor_sync(0xffffffffu, s, 2);
            float sc = __fdividef(pe[srow], s);
            xa.x *= sc; xa.y *= sc; xa.z *= sc; xa.w *= sc;
            xb.x *= sc; xb.y *= sc; xb.z *= sc; xb.w *= sc;
            *(float4*)lr     = xa;
            *(float4*)(lr+4) = xb;
        }
        __syncthreads();

        // ---- stage 3: C2[16b x 128d] += P[16b x 32n] . T[32n x 128d]  (tf32)
        #pragma unroll
        for (int kn = 0; kn < 4; kn++){
            int kn0 = kn*8;
            float p0 = Ls[(br+gid  )*LSTR + kn0 + tin];
            float p1 = Ls[(br+gid+8)*LSTR + kn0 + tin];
            float p2 = Ls[(br+gid  )*LSTR + kn0 + tin + 4];
            float p3 = Ls[(br+gid+8)*LSTR + kn0 + tin + 4];
            unsigned pa0 = f2tf(p0), pa1 = f2tf(p1), pa2 = f2tf(p2), pa3 = f2tf(p3);
            const float* tb0 = Ts + (kn0+tin  )*TSTR + dbase + gid;
            const float* tb1 = Ts + (kn0+tin+4)*TSTR + dbase + gid;
            #pragma unroll
            for (int dt = 0; dt < 16; dt++){
                unsigned ub0 = f2tf(tb0[dt*8]);
                unsigned ub1 = f2tf(tb1[dt*8]);
                mma8(acc[dt].x, acc[dt].y, acc[dt].z, acc[dt].w,
                     pa0, pa1, pa2, pa3, ub0, ub1);
            }
        }
    }

    // epilogue: one atomic sweep per block
    float* comb = out + CB_OFF;
    #pragma unroll
    for (int dt = 0; dt < 16; dt++){
        int d0 = dbase + dt*8 + 2*tin;
        atomicAdd(&comb[(br+gid  )*DIM + d0    ], acc[dt].x);
        atomicAdd(&comb[(br+gid  )*DIM + d0 + 1], acc[dt].y);
        atomicAdd(&comb[(br+gid+8)*DIM + d0    ], acc[dt].z);
        atomicAdd(&comb[(br+gid+8)*DIM + d0 + 1], acc[dt].w);
    }
}

// ---------------------------------------------------------------------------
// K5: o_k = prob_e @ keys_e. block owns 50 m; thread = d; acc over 64 b.
// ---------------------------------------------------------------------------
__global__ __launch_bounds__(256)
void k_ok(const int* __restrict__ keys,
          const float* __restrict__ wordemb,
          float* __restrict__ out){
    __shared__ float pe_s[50*BSZ];
    int tid = threadIdx.x;
    int m0 = blockIdx.x * 50;
    for (int i = tid; i < 50*BSZ; i += 256) pe_s[i] = g_pe[(size_t)m0*BSZ + i];
    __syncthreads();
    int d = tid;
    float acc[BSZ];
    #pragma unroll
    for (int b = 0; b < BSZ; b++) acc[b] = 0.f;
    for (int mm = 0; mm < 50; mm++){
        int id = keys[m0 + mm];
        float ke = (id != 0) ? wordemb[(size_t)id*DIM + d] : 0.f;
        const float4* pr = (const float4*)(pe_s + mm*BSZ);
        #pragma unroll
        for (int b4 = 0; b4 < 16; b4++){
            float4 pv = pr[b4];
            acc[4*b4+0] += pv.x*ke; acc[4*b4+1] += pv.y*ke;
            acc[4*b4+2] += pv.z*ke; acc[4*b4+3] += pv.w*ke;
        }
    }
    float* ok = out + OK_OFF;
    #pragma unroll
    for (int b = 0; b < BSZ; b++) atomicAdd(&ok[b*DIM + d], acc[b]);
}

// ---------------------------------------------------------------------------
extern "C" void kernel_launch(void* const* d_in, const int* in_sizes, int n_in,
                              void* d_out, int out_size){
    const int*   keys    = (const int*)  d_in[0];
    const int*   entries = (const int*)  d_in[1];
    const float* query   = (const float*)d_in[2];
    const float* wordemb = (const float*)d_in[3];
    const float* qw      = (const float*)d_in[4];
    const float* qb      = (const float*)d_in[5];
    float* out = (float*)d_out;

    const int smem_logits = (BSZ*DIM + NTOK*DIM) * 4;      // 98304
    const int smem_main   = MAIN_SMEM_FLOATS * 4;          // 109312
    cudaFuncSetAttribute(k_logits, cudaFuncAttributeMaxDynamicSharedMemorySize, smem_logits);
    cudaFuncSetAttribute(k_main,   cudaFuncAttributeMaxDynamicSharedMemorySize, smem_main);

    k_zero   <<<(BSZ*DIM + 255)/256, 256>>>(out);
    k_vq     <<<BSZ, DIM>>>(query, qw, qb);
    k_logits <<<M_ENT/NTOK, 256, smem_logits>>>(keys, query, wordemb, out);
    k_softmax<<<BSZ, 256>>>(out);
    k_main   <<<296, 256, smem_main>>>(entries, wordemb, out);
    k_ok     <<<M_ENT/50, 256>>>(keys, wordemb, out);
}

// round 17
// speedup vs baseline: 1.1656x; 1.1576x over previous
#include <cuda_runtime.h>

#define M_ENT 8000
#define NTOK  32
#define BSZ   64
#define DIM   256

#define OK_OFF 0
#define LE_OFF (BSZ*DIM)                 // 16384
#define CB_OFF (LE_OFF + BSZ*M_ENT)      // 528384

// scratch (device globals — no allocations allowed)
__device__ float g_vq[BSZ*DIM];     // vq, plain row-major [b][k]
__device__ float g_pe[M_ENT*BSZ];   // prob_e transposed: [m][b]

// ---------------------------------------------------------------------------
// numeric helpers
// ---------------------------------------------------------------------------
__device__ __forceinline__ unsigned f2tf(float v){
    unsigned r; asm("cvt.rna.tf32.f32 %0, %1;" : "=r"(r) : "f"(v)); return r;
}
// pack {lo,hi} floats -> bf16x2 (rn)
__device__ __forceinline__ unsigned packbf(float lo, float hi){
    unsigned r; asm("cvt.rn.bf16x2.f32 %0, %1, %2;" : "=r"(r) : "f"(hi), "f"(lo));
    return r;
}
__device__ __forceinline__ float bf_lo(unsigned h){ return __uint_as_float(h << 16); }
__device__ __forceinline__ float bf_hi(unsigned h){ return __uint_as_float(h & 0xffff0000u); }

// tf32 m16n8k8
__device__ __forceinline__ void mma8(float& c0, float& c1, float& c2, float& c3,
                                     unsigned a0, unsigned a1, unsigned a2, unsigned a3,
                                     unsigned b0, unsigned b1){
    asm volatile("mma.sync.aligned.m16n8k8.row.col.f32.tf32.tf32.f32 "
                 "{%0,%1,%2,%3},{%4,%5,%6,%7},{%8,%9},{%0,%1,%2,%3};"
                 : "+f"(c0), "+f"(c1), "+f"(c2), "+f"(c3)
                 : "r"(a0), "r"(a1), "r"(a2), "r"(a3), "r"(b0), "r"(b1));
}
// bf16 m16n8k16
__device__ __forceinline__ void mma16(float4& c,
                                      unsigned a0, unsigned a1, unsigned a2, unsigned a3,
                                      unsigned b0, unsigned b1){
    asm volatile("mma.sync.aligned.m16n8k16.row.col.f32.bf16.bf16.f32 "
                 "{%0,%1,%2,%3},{%4,%5,%6,%7},{%8,%9},{%0,%1,%2,%3};"
                 : "+f"(c.x), "+f"(c.y), "+f"(c.z), "+f"(c.w)
                 : "r"(a0), "r"(a1), "r"(a2), "r"(a3), "r"(b0), "r"(b1));
}

// ---------------------------------------------------------------------------
// K0: zero the accumulated output regions (o_k, combined)
// ---------------------------------------------------------------------------
__global__ void k_zero(float* out){
    int i = blockIdx.x * blockDim.x + threadIdx.x;
    if (i < BSZ*DIM){ out[OK_OFF + i] = 0.f; out[CB_OFF + i] = 0.f; }
}

// ---------------------------------------------------------------------------
// K1: vq = query @ qproj_w.T + qproj_b  (plain [b][k] layout)
// ---------------------------------------------------------------------------
__global__ void k_vq(const float* __restrict__ query,
                     const float* __restrict__ qw,
                     const float* __restrict__ qb){
    __shared__ float q_s[DIM];
    int b = blockIdx.x, j = threadIdx.x;
    q_s[j] = query[b*DIM + j];
    __syncthreads();
    const float4* w4 = reinterpret_cast<const float4*>(qw) + j*(DIM/4);
    const float4* q4 = reinterpret_cast<const float4*>(q_s);
    float acc = qb[j];
    #pragma unroll 8
    for (int f = 0; f < DIM/4; f++){
        float4 w = w4[f]; float4 q = q4[f];
        acc += w.x*q.x + w.y*q.y + w.z*q.z + w.w*q.w;
    }
    g_vq[b*DIM + j] = acc;
}

// ---------------------------------------------------------------------------
// K2: logits_e[b,m] = query[b] . keys_e[m]  (fp32 — this is an exact output)
// ---------------------------------------------------------------------------
__global__ __launch_bounds__(256)
void k_logits(const int* __restrict__ keys,
              const float* __restrict__ query,
              const float* __restrict__ wordemb,
              float* __restrict__ out){
    extern __shared__ float sm[];
    float* q_s  = sm;               // 16384 floats
    float* ke_s = sm + BSZ*DIM;     // 8192 floats (swizzled)
    int tid = threadIdx.x;
    int m0 = blockIdx.x * NTOK;

    float4* q4s = (float4*)q_s;
    const float4* q4g = (const float4*)query;
    for (int i = tid; i < BSZ*DIM/4; i += 256) q4s[i] = q4g[i];

    {   // gather keys_e (row = lane, quads = warp)
        int n = tid & 31, seg = tid >> 5;
        int id = keys[m0 + n];
        const float4* src = (const float4*)wordemb + (size_t)id*(DIM/4);
        float4* t4 = (float4*)ke_s;
        float4 z = make_float4(0.f,0.f,0.f,0.f);
        #pragma unroll
        for (int q = 0; q < 8; q++){
            int f = seg*8 + q;
            float4 v = (id != 0) ? src[f] : z;
            t4[n*64 + (f ^ (n & 7))] = v;
        }
    }
    __syncthreads();

    int w = tid >> 5, mm = tid & 31;
    const float4* t4 = (const float4*)ke_s;
    const float4* q4 = (const float4*)q_s;
    float lg[8];
    #pragma unroll
    for (int i = 0; i < 8; i++) lg[i] = 0.f;
    #pragma unroll 4
    for (int f = 0; f < 64; f++){
        float4 t = t4[mm*64 + (f ^ (mm & 7))];
        #pragma unroll
        for (int i = 0; i < 8; i++){
            float4 q = q4[(w*8 + i)*64 + f];
            lg[i] += t.x*q.x + t.y*q.y + t.z*q.z + t.w*q.w;
        }
    }
    float* le = out + LE_OFF;
    #pragma unroll
    for (int i = 0; i < 8; i++)
        le[(size_t)(w*8 + i)*M_ENT + m0 + mm] = lg[i];
}

// ---------------------------------------------------------------------------
// K3: row softmax over m; single global read pass (values cached in regs)
// ---------------------------------------------------------------------------
__global__ void k_softmax(const float* __restrict__ out){
    __shared__ float red[256];
    int b = blockIdx.x, tid = threadIdx.x;
    const float* row = out + LE_OFF + (size_t)b*M_ENT;
    float x[32];
    float mx = -3.4e38f;
    #pragma unroll
    for (int i = 0; i < 32; i++){
        int m = tid + 256*i;
        x[i] = (m < M_ENT) ? row[m] : -3.4e38f;
        mx = fmaxf(mx, x[i]);
    }
    red[tid] = mx; __syncthreads();
    for (int s = 128; s; s >>= 1){ if (tid < s) red[tid] = fmaxf(red[tid], red[tid+s]); __syncthreads(); }
    float gmx = red[0];
    __syncthreads();
    float sum = 0.f;
    #pragma unroll
    for (int i = 0; i < 32; i++){
        x[i] = __expf(x[i] - gmx);
        sum += x[i];
    }
    red[tid] = sum; __syncthreads();
    for (int s = 128; s; s >>= 1){ if (tid < s) red[tid] += red[tid+s]; __syncthreads(); }
    float inv = 1.f / red[0];
    #pragma unroll
    for (int i = 0; i < 32; i++){
        int m = tid + 256*i;
        if (m < M_ENT) g_pe[(size_t)m*BSZ + b] = x[i] * inv;
    }
}

// ---------------------------------------------------------------------------
// K4: main. stage1 = split-bf16 m16n8k16 (Vh/Vl precomputed packed in smem,
// Th/Tl packed on the fly). stage3 = single tf32 m16n8k8. C accumulates over
// all entries in regs; one atomic sweep at end.
// warp w: b-tile = (w>>1)*16; stage1 n-half / stage3 d-half = w&1.
// ---------------------------------------------------------------------------
#define VHS  132                       // Vh/Vl row stride (bf16x2 words)
#define TSTR 260
#define LSTR 36
#define VH_SOF 0
#define VL_SOF (BSZ*VHS)               // 8448
#define T_SOF  (2*BSZ*VHS)             // 16896
#define L_SOF  (T_SOF + NTOK*TSTR)     // 25216
#define PE_SOF (L_SOF + BSZ*LSTR)      // 27520
#define MAIN_SMEM_WORDS (PE_SOF + BSZ) // 27584 -> 110336 B

__global__ __launch_bounds__(256, 2)
void k_main(const int* __restrict__ entries,
            const float* __restrict__ wordemb,
            float* __restrict__ out){
    extern __shared__ float sm[];
    unsigned* Vh = (unsigned*)(sm + VH_SOF);
    unsigned* Vl = (unsigned*)(sm + VL_SOF);
    float*    Ts = sm + T_SOF;
    float*    Ls = sm + L_SOF;
    float*    pe = sm + PE_SOF;
    int tid = threadIdx.x, w = tid >> 5, lane = tid & 31;
    int gid = lane >> 2, tin = lane & 3;

    // precompute V as packed bf16x2 high/low halves (once per block)
    for (int p = tid; p < BSZ*128; p += 256){
        int b = p >> 7, kp = p & 127;
        float2 v = ((const float2*)g_vq)[p];
        unsigned h = packbf(v.x, v.y);
        float l0 = v.x - bf_lo(h);
        float l1 = v.y - bf_hi(h);
        Vh[b*VHS + kp] = h;
        Vl[b*VHS + kp] = packbf(l0, l1);
    }

    const int br    = (w >> 1) * 16;   // b-tile base
    const int nh    = (w & 1);         // stage1 n-half
    const int dbase = (w & 1) * 128;   // stage3 d-half

    float4 acc[16];                    // C: 16b x 128d per warp
    #pragma unroll
    for (int i = 0; i < 16; i++) acc[i] = make_float4(0.f,0.f,0.f,0.f);

    const unsigned* vhr0 = Vh + (br+gid  )*VHS + tin;
    const unsigned* vhr1 = Vh + (br+gid+8)*VHS + tin;
    const unsigned* vlr0 = Vl + (br+gid  )*VHS + tin;
    const unsigned* vlr1 = Vl + (br+gid+8)*VHS + tin;
    const float*    tr0  = Ts + (nh*16+gid  )*TSTR + 2*tin;
    const float*    tr1  = Ts + (nh*16+8+gid)*TSTR + 2*tin;

    for (int m = blockIdx.x; m < M_ENT; m += gridDim.x){
        __syncthreads();   // protect Ts/Ls from previous iteration readers
        {   // gather entry token tile (row = lane), mask pad idx
            int id = entries[m*NTOK + lane];
            const float4* src = (const float4*)wordemb + (size_t)id*(DIM/4);
            float4 z = make_float4(0.f,0.f,0.f,0.f);
            float4* dst = (float4*)(Ts + lane*TSTR);
            #pragma unroll
            for (int q = 0; q < 8; q++){
                int f = w*8 + q;
                dst[f] = (id != 0) ? src[f] : z;
            }
        }
        if (tid < BSZ) pe[tid] = g_pe[(size_t)m*BSZ + tid];
        __syncthreads();

        // ---- stage 1: L[16b x 16n] = V . T^T, split-bf16 (VhTh + VlTh + VhTl)
        float4 L0 = make_float4(0.f,0.f,0.f,0.f);
        float4 L1 = make_float4(0.f,0.f,0.f,0.f);
        #pragma unroll 4
        for (int ki = 0; ki < 16; ki++){
            int kp = 8*ki;
            unsigned ah0 = vhr0[kp],   ah1 = vhr1[kp];
            unsigned ah2 = vhr0[kp+4], ah3 = vhr1[kp+4];
            unsigned al0 = vlr0[kp],   al1 = vlr1[kp];
            unsigned al2 = vlr0[kp+4], al3 = vlr1[kp+4];
            // n-subtile 0
            {
                float2 t0 = *(const float2*)&tr0[16*ki];
                float2 t1 = *(const float2*)&tr0[16*ki + 8];
                unsigned bh0 = packbf(t0.x, t0.y);
                unsigned bh1 = packbf(t1.x, t1.y);
                unsigned bl0 = packbf(t0.x - bf_lo(bh0), t0.y - bf_hi(bh0));
                unsigned bl1 = packbf(t1.x - bf_lo(bh1), t1.y - bf_hi(bh1));
                mma16(L0, ah0,ah1,ah2,ah3, bh0,bh1);
                mma16(L0, al0,al1,al2,al3, bh0,bh1);
                mma16(L0, ah0,ah1,ah2,ah3, bl0,bl1);
            }
            // n-subtile 1
            {
                float2 t0 = *(const float2*)&tr1[16*ki];
                float2 t1 = *(const float2*)&tr1[16*ki + 8];
                unsigned bh0 = packbf(t0.x, t0.y);
                unsigned bh1 = packbf(t1.x, t1.y);
                unsigned bl0 = packbf(t0.x - bf_lo(bh0), t0.y - bf_hi(bh0));
                unsigned bl1 = packbf(t1.x - bf_lo(bh1), t1.y - bf_hi(bh1));
                mma16(L1, ah0,ah1,ah2,ah3, bh0,bh1);
                mma16(L1, al0,al1,al2,al3, bh0,bh1);
                mma16(L1, ah0,ah1,ah2,ah3, bl0,bl1);
            }
        }
        {   // write logits to smem (C-frag layout)
            float* lw0 = Ls + (br+gid)*LSTR;
            float* lw1 = Ls + (br+gid+8)*LSTR;
            int nc = nh*16 + 2*tin;
            lw0[nc]   = L0.x; lw0[nc+1] = L0.y;
            lw1[nc]   = L0.z; lw1[nc+1] = L0.w;
            lw0[nc+8] = L1.x; lw0[nc+9] = L1.y;
            lw1[nc+8] = L1.z; lw1[nc+9] = L1.w;
        }
        __syncthreads();

        // ---- softmax over 32 tokens per b row; fold in prob_e; in place.
        {
            int srow = w*8 + (lane >> 2);
            float* lr = Ls + srow*LSTR + (lane & 3)*8;
            float4 xa = *(float4*)lr;
            float4 xb = *(float4*)(lr + 4);
            float mx = fmaxf(fmaxf(fmaxf(xa.x,xa.y), fmaxf(xa.z,xa.w)),
                             fmaxf(fmaxf(xb.x,xb.y), fmaxf(xb.z,xb.w)));
            mx = fmaxf(mx, __shfl_xor_sync(0xffffffffu, mx, 1));
            mx = fmaxf(mx, __shfl_xor_sync(0xffffffffu, mx, 2));
            xa.x = __expf(xa.x - mx); xa.y = __expf(xa.y - mx);
            xa.z = __expf(xa.z - mx); xa.w = __expf(xa.w - mx);
            xb.x = __expf(xb.x - mx); xb.y = __expf(xb.y - mx);
            xb.z = __expf(xb.z - mx); xb.w = __expf(xb.w - mx);
            float s = (xa.x+xa.y+xa.z+xa.w) + (xb.x+xb.y+xb.z+xb.w);
            s += __shfl_xor_sync(0xffffffffu, s, 1);
            s += __shfl_xor_sync(0xffffffffu, s, 2);
            float sc = __fdividef(pe[srow], s);
            xa.x *= sc; xa.y *= sc; xa.z *= sc; xa.w *= sc;
            xb.x *= sc; xb.y *= sc; xb.z *= sc; xb.w *= sc;
            *(float4*)lr     = xa;
            *(float4*)(lr+4) = xb;
        }
        __syncthreads();

        // ---- stage 3: C[16b x 128d] += P[16b x 32n] . T[32n x 128d]  (tf32)
        #pragma unroll
        for (int kn = 0; kn < 4; kn++){
            int kn0 = kn*8;
            float p0 = Ls[(br+gid  )*LSTR + kn0 + tin];
            float p1 = Ls[(br+gid+8)*LSTR + kn0 + tin];
            float p2 = Ls[(br+gid  )*LSTR + kn0 + tin + 4];
            float p3 = Ls[(br+gid+8)*LSTR + kn0 + tin + 4];
            unsigned pa0 = f2tf(p0), pa1 = f2tf(p1), pa2 = f2tf(p2), pa3 = f2tf(p3);
            const float* tb0 = Ts + (kn0+tin  )*TSTR + dbase + gid;
            const float* tb1 = Ts + (kn0+tin+4)*TSTR + dbase + gid;
            #pragma unroll
            for (int dt = 0; dt < 16; dt++){
                unsigned ub0 = f2tf(tb0[dt*8]);
                unsigned ub1 = f2tf(tb1[dt*8]);
                mma8(acc[dt].x, acc[dt].y, acc[dt].z, acc[dt].w,
                     pa0, pa1, pa2, pa3, ub0, ub1);
            }
        }
    }

    // epilogue: one atomic sweep per block
    float* comb = out + CB_OFF;
    #pragma unroll
    for (int dt = 0; dt < 16; dt++){
        int d0 = dbase + dt*8 + 2*tin;
        atomicAdd(&comb[(br+gid  )*DIM + d0    ], acc[dt].x);
        atomicAdd(&comb[(br+gid  )*DIM + d0 + 1], acc[dt].y);
        atomicAdd(&comb[(br+gid+8)*DIM + d0    ], acc[dt].z);
        atomicAdd(&comb[(br+gid+8)*DIM + d0 + 1], acc[dt].w);
    }
}

// ---------------------------------------------------------------------------
// K5: o_k = prob_e @ keys_e. block owns 50 m; thread = d; acc over 64 b.
// ---------------------------------------------------------------------------
__global__ __launch_bounds__(256)
void k_ok(const int* __restrict__ keys,
          const float* __restrict__ wordemb,
          float* __restrict__ out){
    __shared__ float pe_s[50*BSZ];
    int tid = threadIdx.x;
    int m0 = blockIdx.x * 50;
    for (int i = tid; i < 50*BSZ; i += 256) pe_s[i] = g_pe[(size_t)m0*BSZ + i];
    __syncthreads();
    int d = tid;
    float acc[BSZ];
    #pragma unroll
    for (int b = 0; b < BSZ; b++) acc[b] = 0.f;
    for (int mm = 0; mm < 50; mm++){
        int id = keys[m0 + mm];
        float ke = (id != 0) ? wordemb[(size_t)id*DIM + d] : 0.f;
        const float4* pr = (const float4*)(pe_s + mm*BSZ);
        #pragma unroll
        for (int b4 = 0; b4 < 16; b4++){
            float4 pv = pr[b4];
            acc[4*b4+0] += pv.x*ke; acc[4*b4+1] += pv.y*ke;
            acc[4*b4+2] += pv.z*ke; acc[4*b4+3] += pv.w*ke;
        }
    }
    float* ok = out + OK_OFF;
    #pragma unroll
    for (int b = 0; b < BSZ; b++) atomicAdd(&ok[b*DIM + d], acc[b]);
}

// ---------------------------------------------------------------------------
extern "C" void kernel_launch(void* const* d_in, const int* in_sizes, int n_in,
                              void* d_out, int out_size){
    const int*   keys    = (const int*)  d_in[0];
    const int*   entries = (const int*)  d_in[1];
    const float* query   = (const float*)d_in[2];
    const float* wordemb = (const float*)d_in[3];
    const float* qw      = (const float*)d_in[4];
    const float* qb      = (const float*)d_in[5];
    float* out = (float*)d_out;

    const int smem_logits = (BSZ*DIM + NTOK*DIM) * 4;      // 98304
    const int smem_main   = MAIN_SMEM_WORDS * 4;           // 110336
    cudaFuncSetAttribute(k_logits, cudaFuncAttributeMaxDynamicSharedMemorySize, smem_logits);
    cudaFuncSetAttribute(k_main,   cudaFuncAttributeMaxDynamicSharedMemorySize, smem_main);

    k_zero   <<<(BSZ*DIM + 255)/256, 256>>>(out);
    k_vq     <<<BSZ, DIM>>>(query, qw, qb);
    k_logits <<<M_ENT/NTOK, 256, smem_logits>>>(keys, query, wordemb, out);
    k_softmax<<<BSZ, 256>>>(out);
    k_ok     <<<M_ENT/50, 256>>>(keys, wordemb, out);   // moved before k_main
    k_main   <<<296, 256, smem_main>>>(entries, wordemb, out);
}